// round 6
// baseline (speedup 1.0000x reference)
#include <cuda_runtime.h>
#include <cuda_bf16.h>
#include <cstdint>

// Problem constants (shapes fixed by the dataset; N/E derived at runtime from in_sizes)
#define MAXN 100000
#define CIN  256
#define COUT 64

// Scratch (device globals: no allocation allowed in kernel_launch).
// float4-typed so vector loads / vector reductions are guaranteed 16B-aligned
// and live in module global space (safe for red.global).
__device__ int    g_deg[MAXN];
__device__ float  g_dinv[MAXN];
__device__ float4 g_hs [(size_t)MAXN * (COUT / 4)];   // hs = (x @ W) * dinv[row]
__device__ float4 g_acc[(size_t)MAXN * (COUT / 4)];   // scatter accumulator

// ---------------------------------------------------------------------------
// K0: zero accumulator + degree counters
// ---------------------------------------------------------------------------
__global__ void zero_kernel(int N) {
    int i = blockIdx.x * blockDim.x + threadIdx.x;
    int total = N * (COUT / 4);
    if (i < total) g_acc[i] = make_float4(0.f, 0.f, 0.f, 0.f);
    if (i < N) g_deg[i] = 0;
}

// ---------------------------------------------------------------------------
// K1: count in-degree on destination nodes (edge_index is INT32: JAX x64 off)
// ---------------------------------------------------------------------------
__global__ void count_deg_kernel(const int* __restrict__ ei, int E) {
    int e = blockIdx.x * blockDim.x + threadIdx.x;
    if (e < E) {
        int d = ei[(size_t)E + e];   // edge_index[1][e]
        atomicAdd(&g_deg[d], 1);
    }
}

// ---------------------------------------------------------------------------
// K2: dinv = rsqrt(deg + 1)   (+1 = self loop; always > 0)
// ---------------------------------------------------------------------------
__global__ void dinv_kernel(int N) {
    int i = blockIdx.x * blockDim.x + threadIdx.x;
    if (i < N) g_dinv[i] = rsqrtf((float)(g_deg[i] + 1));
}

// ---------------------------------------------------------------------------
// K3: GEMM  hs[r][c] = dinv[r] * sum_k x[r][k] * W[k][c]
// Block: 256 threads, tile = 128 rows x 64 cols.
// Thread: 4 rows x 8 cols register tile. W staged in smem in two 128-k halves.
// ---------------------------------------------------------------------------
__global__ __launch_bounds__(256) void gemm_kernel(
    const float* __restrict__ x, const float* __restrict__ W, int N)
{
    __shared__ float4 Ws[128 * 16];   // 128 k-rows x 64 cols = 32 KB

    const int tid = threadIdx.x;
    const int cg  = tid & 7;          // col group: cols cg*8 .. cg*8+7
    const int rg  = tid >> 3;         // row group 0..31
    const int rowBase = blockIdx.x * 128 + rg * 4;

    float acc[4][8];
#pragma unroll
    for (int i = 0; i < 4; i++)
#pragma unroll
        for (int c = 0; c < 8; c++) acc[i][c] = 0.0f;

    const float4* x4 = reinterpret_cast<const float4*>(x);
    const float4* W4 = reinterpret_cast<const float4*>(W);

    bool valid[4];
#pragma unroll
    for (int i = 0; i < 4; i++) valid[i] = (rowBase + i) < N;

    for (int ph = 0; ph < 2; ++ph) {
        __syncthreads();
        // stage W[ph*128 .. ph*128+128][:] -> smem (2048 float4, 8 per thread)
        for (int i = tid; i < 2048; i += 256)
            Ws[i] = W4[ph * 2048 + i];
        __syncthreads();

#pragma unroll 4
        for (int k4 = 0; k4 < 32; ++k4) {
            const int kq = ph * 32 + k4;   // float4 index along k within an x row
            float4 xv[4];
#pragma unroll
            for (int i = 0; i < 4; i++) {
                xv[i] = valid[i] ? x4[(size_t)(rowBase + i) * (CIN / 4) + kq]
                                 : make_float4(0.f, 0.f, 0.f, 0.f);
            }
#pragma unroll
            for (int j = 0; j < 4; j++) {
                const float4 wa = Ws[(k4 * 4 + j) * 16 + cg * 2];
                const float4 wb = Ws[(k4 * 4 + j) * 16 + cg * 2 + 1];
#pragma unroll
                for (int i = 0; i < 4; i++) {
                    const float s = (j == 0) ? xv[i].x :
                                    (j == 1) ? xv[i].y :
                                    (j == 2) ? xv[i].z : xv[i].w;
                    acc[i][0] += s * wa.x;
                    acc[i][1] += s * wa.y;
                    acc[i][2] += s * wa.z;
                    acc[i][3] += s * wa.w;
                    acc[i][4] += s * wb.x;
                    acc[i][5] += s * wb.y;
                    acc[i][6] += s * wb.z;
                    acc[i][7] += s * wb.w;
                }
            }
        }
    }

    // Epilogue: scale by dinv[row], write hs
#pragma unroll
    for (int i = 0; i < 4; i++) {
        const int r = rowBase + i;
        if (r < N) {
            const float dv = g_dinv[r];
            g_hs[(size_t)r * (COUT / 4) + cg * 2] =
                make_float4(acc[i][0] * dv, acc[i][1] * dv,
                            acc[i][2] * dv, acc[i][3] * dv);
            g_hs[(size_t)r * (COUT / 4) + cg * 2 + 1] =
                make_float4(acc[i][4] * dv, acc[i][5] * dv,
                            acc[i][6] * dv, acc[i][7] * dv);
        }
    }
}

// ---------------------------------------------------------------------------
// K4: edge scatter  acc[dst] += hs[src]   (norms pre-folded into hs/finalize)
// 16 threads per edge, one float4 each; vector reduction red.global.add.v4.f32
// into our own module-global accumulator (never into harness memory).
// ---------------------------------------------------------------------------
__global__ __launch_bounds__(256) void scatter_kernel(
    const int* __restrict__ ei, int E)
{
    const long long idx = (long long)blockIdx.x * blockDim.x + threadIdx.x;
    const long long e = idx >> 4;
    if (e >= E) return;
    const int c = (int)(idx & 15);

    const int s = __ldg(&ei[e]);
    const int d = __ldg(&ei[(size_t)E + e]);

    const float4 v = __ldg(&g_hs[(size_t)s * (COUT / 4) + c]);
    float4* dst = &g_acc[(size_t)d * (COUT / 4) + c];
    asm volatile("red.global.add.v4.f32 [%0], {%1, %2, %3, %4};"
                 :: "l"(dst), "f"(v.x), "f"(v.y), "f"(v.z), "f"(v.w)
                 : "memory");
}

// ---------------------------------------------------------------------------
// K5: finalize  out[r][c] = dinv[r] * (acc[r][c] + hs[r][c]) + b[c]
// (the +hs term is the self loop: dinv[r]^2 * h[r]). Plain stores to d_out.
// ---------------------------------------------------------------------------
__global__ __launch_bounds__(256) void finalize_kernel(
    const float* __restrict__ b, float* __restrict__ out, int N)
{
    const int i4 = blockIdx.x * blockDim.x + threadIdx.x;   // float4 index
    if (i4 >= N * (COUT / 4)) return;
    const int r  = i4 >> 4;
    const int c4 = i4 & 15;

    const float4* b4 = reinterpret_cast<const float4*>(b);

    const float dv = g_dinv[r];
    const float4 o  = g_acc[i4];
    const float4 h  = g_hs[i4];
    const float4 bb = __ldg(&b4[c4]);

    float4 res = make_float4(dv * (o.x + h.x) + bb.x,
                             dv * (o.y + h.y) + bb.y,
                             dv * (o.z + h.z) + bb.z,
                             dv * (o.w + h.w) + bb.w);
    reinterpret_cast<float4*>(out)[i4] = res;
}

// ---------------------------------------------------------------------------
// Launch
// ---------------------------------------------------------------------------
extern "C" void kernel_launch(void* const* d_in, const int* in_sizes, int n_in,
                              void* d_out, int out_size) {
    const float* x  = (const float*)d_in[0];
    const int*   ei = (const int*)d_in[1];     // edge_index is int32 (JAX x64 off)
    const float* W  = (const float*)d_in[2];
    const float* b  = (const float*)d_in[3];
    float*       out = (float*)d_out;

    const int N = in_sizes[0] / CIN;
    const int E = in_sizes[1] / 2;

    zero_kernel<<<(N * (COUT / 4) + 255) / 256, 256>>>(N);
    count_deg_kernel<<<(E + 255) / 256, 256>>>(ei, E);
    dinv_kernel<<<(N + 255) / 256, 256>>>(N);
    gemm_kernel<<<(N + 127) / 128, 256>>>(x, W, N);

    const long long scatter_threads = (long long)E * 16;
    scatter_kernel<<<(unsigned)((scatter_threads + 255) / 256), 256>>>(ei, E);

    finalize_kernel<<<(N * (COUT / 4) + 255) / 256, 256>>>(b, out, N);
}

// round 7
// speedup vs baseline: 1.9291x; 1.9291x over previous
#include <cuda_runtime.h>
#include <cuda_bf16.h>
#include <cstdint>

// Problem constants (shapes fixed by the dataset; N/E derived at runtime from in_sizes)
#define MAXN 100000
#define CIN  256
#define COUT 64

// Scratch (device globals: no allocation allowed in kernel_launch).
__device__ int    g_deg[MAXN];
__device__ float  g_dinv[MAXN];
__device__ float4 g_hs [(size_t)MAXN * (COUT / 4)];   // hs = (x @ W) * dinv[row]
__device__ float4 g_acc[(size_t)MAXN * (COUT / 4)];   // scatter accumulator

// ---------------------------------------------------------------------------
// K0: zero accumulator + degree counters
// ---------------------------------------------------------------------------
__global__ void zero_kernel(int N) {
    int i = blockIdx.x * blockDim.x + threadIdx.x;
    int total = N * (COUT / 4);
    if (i < total) g_acc[i] = make_float4(0.f, 0.f, 0.f, 0.f);
    if (i < N) g_deg[i] = 0;
}

// ---------------------------------------------------------------------------
// K1: count in-degree on destination nodes (edge_index is INT32: JAX x64 off)
// ---------------------------------------------------------------------------
__global__ void count_deg_kernel(const int* __restrict__ ei, int E) {
    int e = blockIdx.x * blockDim.x + threadIdx.x;
    if (e < E) {
        int d = ei[(size_t)E + e];   // edge_index[1][e]
        atomicAdd(&g_deg[d], 1);
    }
}

// ---------------------------------------------------------------------------
// K2: dinv = rsqrt(deg + 1)   (+1 = self loop; always > 0)
// ---------------------------------------------------------------------------
__global__ void dinv_kernel(int N) {
    int i = blockIdx.x * blockDim.x + threadIdx.x;
    if (i < N) g_dinv[i] = rsqrtf((float)(g_deg[i] + 1));
}

// ---------------------------------------------------------------------------
// K3: tf32 tensor-core GEMM  hs[r][c] = dinv[r] * sum_k x[r][k] * W[k][c]
//
// 256 threads = 8 warps; block tile 128 rows x 64 cols; warp tile 32x32
// (2 m-tiles x 4 n-tiles of m16n8k8). K split into 8 phases of 32.
// x and W are staged in smem already converted to tf32 bit patterns.
// Smem strides are chosen for conflict-free fragment loads:
//   A frag: bank = (4*gid + tig) % 32  -> 32 distinct
//   B frag: bank = (8*tig + gid) % 32  -> 32 distinct
// ---------------------------------------------------------------------------
#define SKX 36   // xs row stride in u32 (32 k + 4 pad); 144 B, 16B-aligned
#define SNW 72   // ws row stride in u32 (64 n + 8 pad); 288 B, 16B-aligned

__device__ __forceinline__ uint32_t f2tf32(float f) {
    uint32_t r;
    asm("cvt.rna.tf32.f32 %0, %1;" : "=r"(r) : "f"(f));
    return r;
}

__global__ __launch_bounds__(256) void gemm_tf32_kernel(
    const float* __restrict__ x, const float* __restrict__ W, int N)
{
    __shared__ uint32_t xs[128 * SKX];   // 18432 B : x tile [row][k], tf32 bits
    __shared__ uint32_t ws[32 * SNW];    //  9216 B : W tile [k][n],   tf32 bits

    const int tid  = threadIdx.x;
    const int wid  = tid >> 5;
    const int lane = tid & 31;
    const int wm   = wid >> 1;        // warp m index 0..3
    const int wn   = wid & 1;         // warp n index 0..1
    const int gid  = lane >> 2;       // groupID 0..7
    const int tig  = lane & 3;        // thread-in-group 0..3

    const int rowBase = blockIdx.x * 128;

    float c[2][4][4];
#pragma unroll
    for (int mt = 0; mt < 2; mt++)
#pragma unroll
        for (int nt = 0; nt < 4; nt++)
#pragma unroll
            for (int r = 0; r < 4; r++) c[mt][nt][r] = 0.f;

    const float4* x4 = reinterpret_cast<const float4*>(x);
    const float4* W4 = reinterpret_cast<const float4*>(W);

    for (int ph = 0; ph < 8; ++ph) {
        __syncthreads();
        // ---- stage x: 128 rows x 32 k = 1024 float4, 4 per thread ----
#pragma unroll
        for (int i = 0; i < 4; ++i) {
            const int f   = tid + 256 * i;
            const int row = f >> 3;
            const int kq  = f & 7;
            const int r   = rowBase + row;
            float4 v = (r < N) ? x4[(size_t)r * (CIN / 4) + ph * 8 + kq]
                               : make_float4(0.f, 0.f, 0.f, 0.f);
            uint4 t;
            t.x = f2tf32(v.x); t.y = f2tf32(v.y);
            t.z = f2tf32(v.z); t.w = f2tf32(v.w);
            *reinterpret_cast<uint4*>(&xs[row * SKX + kq * 4]) = t;
        }
        // ---- stage W: 32 k x 64 n = 512 float4, 2 per thread ----
#pragma unroll
        for (int i = 0; i < 2; ++i) {
            const int f  = tid + 256 * i;
            const int k  = f >> 4;
            const int nq = f & 15;
            float4 v = W4[(size_t)(ph * 32 + k) * (COUT / 4) + nq];
            uint4 t;
            t.x = f2tf32(v.x); t.y = f2tf32(v.y);
            t.z = f2tf32(v.z); t.w = f2tf32(v.w);
            *reinterpret_cast<uint4*>(&ws[k * SNW + nq * 4]) = t;
        }
        __syncthreads();

        // ---- mma over 4 k8-steps ----
#pragma unroll
        for (int k8 = 0; k8 < 4; ++k8) {
            const int k0 = k8 * 8;
            uint32_t a[2][4], b[4][2];
#pragma unroll
            for (int mt = 0; mt < 2; ++mt) {
                const int m0 = wm * 32 + mt * 16;
                a[mt][0] = xs[(m0 + gid    ) * SKX + k0 + tig    ];
                a[mt][1] = xs[(m0 + 8 + gid) * SKX + k0 + tig    ];
                a[mt][2] = xs[(m0 + gid    ) * SKX + k0 + 4 + tig];
                a[mt][3] = xs[(m0 + 8 + gid) * SKX + k0 + 4 + tig];
            }
#pragma unroll
            for (int nt = 0; nt < 4; ++nt) {
                const int n0 = wn * 32 + nt * 8;
                b[nt][0] = ws[(k0 + tig    ) * SNW + n0 + gid];
                b[nt][1] = ws[(k0 + 4 + tig) * SNW + n0 + gid];
            }
#pragma unroll
            for (int mt = 0; mt < 2; ++mt)
#pragma unroll
                for (int nt = 0; nt < 4; ++nt) {
                    asm volatile(
                        "mma.sync.aligned.m16n8k8.row.col.f32.tf32.tf32.f32 "
                        "{%0,%1,%2,%3}, {%4,%5,%6,%7}, {%8,%9}, {%0,%1,%2,%3};"
                        : "+f"(c[mt][nt][0]), "+f"(c[mt][nt][1]),
                          "+f"(c[mt][nt][2]), "+f"(c[mt][nt][3])
                        : "r"(a[mt][0]), "r"(a[mt][1]),
                          "r"(a[mt][2]), "r"(a[mt][3]),
                          "r"(b[nt][0]), "r"(b[nt][1]));
                }
        }
    }

    // ---- epilogue: scale by dinv, store as float2 pairs ----
    float2* hs2 = reinterpret_cast<float2*>(g_hs);
#pragma unroll
    for (int mt = 0; mt < 2; ++mt) {
        const int r0 = rowBase + wm * 32 + mt * 16 + gid;
        const int r1 = r0 + 8;
        const float dv0 = (r0 < N) ? g_dinv[r0] : 0.f;
        const float dv1 = (r1 < N) ? g_dinv[r1] : 0.f;
#pragma unroll
        for (int nt = 0; nt < 4; ++nt) {
            const int cpair = wn * 16 + nt * 4 + tig;   // float2 index, 0..31
            if (r0 < N)
                hs2[(size_t)r0 * (COUT / 2) + cpair] =
                    make_float2(c[mt][nt][0] * dv0, c[mt][nt][1] * dv0);
            if (r1 < N)
                hs2[(size_t)r1 * (COUT / 2) + cpair] =
                    make_float2(c[mt][nt][2] * dv1, c[mt][nt][3] * dv1);
        }
    }
}

// ---------------------------------------------------------------------------
// K4: edge scatter  acc[dst] += hs[src]   (norms pre-folded into hs/finalize)
// 16 threads per edge, one float4 each; vector reduction red.global.add.v4.f32
// ---------------------------------------------------------------------------
__global__ __launch_bounds__(256) void scatter_kernel(
    const int* __restrict__ ei, int E)
{
    const long long idx = (long long)blockIdx.x * blockDim.x + threadIdx.x;
    const long long e = idx >> 4;
    if (e >= E) return;
    const int c = (int)(idx & 15);

    const int s = __ldg(&ei[e]);
    const int d = __ldg(&ei[(size_t)E + e]);

    const float4 v = __ldg(&g_hs[(size_t)s * (COUT / 4) + c]);
    float4* dst = &g_acc[(size_t)d * (COUT / 4) + c];
    asm volatile("red.global.add.v4.f32 [%0], {%1, %2, %3, %4};"
                 :: "l"(dst), "f"(v.x), "f"(v.y), "f"(v.z), "f"(v.w)
                 : "memory");
}

// ---------------------------------------------------------------------------
// K5: finalize  out[r][c] = dinv[r] * (acc[r][c] + hs[r][c]) + b[c]
// ---------------------------------------------------------------------------
__global__ __launch_bounds__(256) void finalize_kernel(
    const float* __restrict__ b, float* __restrict__ out, int N)
{
    const int i4 = blockIdx.x * blockDim.x + threadIdx.x;   // float4 index
    if (i4 >= N * (COUT / 4)) return;
    const int r  = i4 >> 4;
    const int c4 = i4 & 15;

    const float4* b4 = reinterpret_cast<const float4*>(b);

    const float dv = g_dinv[r];
    const float4 o  = g_acc[i4];
    const float4 h  = g_hs[i4];
    const float4 bb = __ldg(&b4[c4]);

    float4 res = make_float4(dv * (o.x + h.x) + bb.x,
                             dv * (o.y + h.y) + bb.y,
                             dv * (o.z + h.z) + bb.z,
                             dv * (o.w + h.w) + bb.w);
    reinterpret_cast<float4*>(out)[i4] = res;
}

// ---------------------------------------------------------------------------
// Launch
// ---------------------------------------------------------------------------
extern "C" void kernel_launch(void* const* d_in, const int* in_sizes, int n_in,
                              void* d_out, int out_size) {
    const float* x  = (const float*)d_in[0];
    const int*   ei = (const int*)d_in[1];     // edge_index is int32 (JAX x64 off)
    const float* W  = (const float*)d_in[2];
    const float* b  = (const float*)d_in[3];
    float*       out = (float*)d_out;

    const int N = in_sizes[0] / CIN;
    const int E = in_sizes[1] / 2;

    zero_kernel<<<(N * (COUT / 4) + 255) / 256, 256>>>(N);
    count_deg_kernel<<<(E + 255) / 256, 256>>>(ei, E);
    dinv_kernel<<<(N + 255) / 256, 256>>>(N);
    gemm_tf32_kernel<<<(N + 127) / 128, 256>>>(x, W, N);

    const long long scatter_threads = (long long)E * 16;
    scatter_kernel<<<(unsigned)((scatter_threads + 255) / 256), 256>>>(ei, E);

    finalize_kernel<<<(N * (COUT / 4) + 255) / 256, 256>>>(b, out, N);
}

// round 9
// speedup vs baseline: 3.3813x; 1.7528x over previous
#include <cuda_runtime.h>
#include <cuda_bf16.h>
#include <cstdint>

// Problem constants (shapes fixed by the dataset; N/E derived at runtime from in_sizes)
#define MAXN 100000
#define CIN  256
#define COUT 64
#define CAP  192     // per-node adjacency bucket capacity (deg ~ Poisson(32); 17+ sigma)

// Scratch (device globals: no allocation allowed in kernel_launch).
__device__ int    g_deg[MAXN];                        // degree / bucket cursor
__device__ float  g_dinv[MAXN];
__device__ float4 g_hs [(size_t)MAXN * (COUT / 4)];   // hs = (x @ W) * dinv[row]
__device__ int    g_csr[(size_t)MAXN * CAP];          // bucketed CSR: src ids per dst

// ---------------------------------------------------------------------------
// K0: zero bucket cursors
// ---------------------------------------------------------------------------
__global__ void zero_deg_kernel(int N) {
    int i = blockIdx.x * blockDim.x + threadIdx.x;
    if (i < N) g_deg[i] = 0;
}

// ---------------------------------------------------------------------------
// K1: bucketed CSR fill (also produces in-degree). edge_index is INT32.
// ---------------------------------------------------------------------------
__global__ __launch_bounds__(256) void csr_fill_kernel(const int* __restrict__ ei, int E) {
    int e = blockIdx.x * blockDim.x + threadIdx.x;
    if (e < E) {
        const int s = __ldg(&ei[e]);
        const int d = __ldg(&ei[(size_t)E + e]);
        const int pos = atomicAdd(&g_deg[d], 1);
        if (pos < CAP) g_csr[d * CAP + pos] = s;
    }
}

// ---------------------------------------------------------------------------
// K2: dinv = rsqrt(deg + 1)   (+1 = self loop; always > 0)
// ---------------------------------------------------------------------------
__global__ void dinv_kernel(int N) {
    int i = blockIdx.x * blockDim.x + threadIdx.x;
    if (i < N) g_dinv[i] = rsqrtf((float)(g_deg[i] + 1));
}

// ---------------------------------------------------------------------------
// K3: tf32 tensor-core GEMM  hs[r][c] = dinv[r] * sum_k x[r][k] * W[k][c]
// 256 threads = 8 warps; block tile 128x64; warp tile 32x32 (m16n8k8).
// Conflict-free smem strides: SKX=36, SNW=72.
// ---------------------------------------------------------------------------
#define SKX 36
#define SNW 72

__device__ __forceinline__ uint32_t f2tf32(float f) {
    uint32_t r;
    asm("cvt.rna.tf32.f32 %0, %1;" : "=r"(r) : "f"(f));
    return r;
}

__global__ __launch_bounds__(256) void gemm_tf32_kernel(
    const float* __restrict__ x, const float* __restrict__ W, int N)
{
    __shared__ uint32_t xs[128 * SKX];
    __shared__ uint32_t ws[32 * SNW];

    const int tid  = threadIdx.x;
    const int wid  = tid >> 5;
    const int lane = tid & 31;
    const int wm   = wid >> 1;
    const int wn   = wid & 1;
    const int gid  = lane >> 2;
    const int tig  = lane & 3;

    const int rowBase = blockIdx.x * 128;

    float c[2][4][4];
#pragma unroll
    for (int mt = 0; mt < 2; mt++)
#pragma unroll
        for (int nt = 0; nt < 4; nt++)
#pragma unroll
            for (int r = 0; r < 4; r++) c[mt][nt][r] = 0.f;

    const float4* x4 = reinterpret_cast<const float4*>(x);
    const float4* W4 = reinterpret_cast<const float4*>(W);

    for (int ph = 0; ph < 8; ++ph) {
        __syncthreads();
#pragma unroll
        for (int i = 0; i < 4; ++i) {
            const int f   = tid + 256 * i;
            const int row = f >> 3;
            const int kq  = f & 7;
            const int r   = rowBase + row;
            float4 v = (r < N) ? x4[(size_t)r * (CIN / 4) + ph * 8 + kq]
                               : make_float4(0.f, 0.f, 0.f, 0.f);
            uint4 t;
            t.x = f2tf32(v.x); t.y = f2tf32(v.y);
            t.z = f2tf32(v.z); t.w = f2tf32(v.w);
            *reinterpret_cast<uint4*>(&xs[row * SKX + kq * 4]) = t;
        }
#pragma unroll
        for (int i = 0; i < 2; ++i) {
            const int f  = tid + 256 * i;
            const int k  = f >> 4;
            const int nq = f & 15;
            float4 v = W4[(size_t)(ph * 32 + k) * (COUT / 4) + nq];
            uint4 t;
            t.x = f2tf32(v.x); t.y = f2tf32(v.y);
            t.z = f2tf32(v.z); t.w = f2tf32(v.w);
            *reinterpret_cast<uint4*>(&ws[k * SNW + nq * 4]) = t;
        }
        __syncthreads();

#pragma unroll
        for (int k8 = 0; k8 < 4; ++k8) {
            const int k0 = k8 * 8;
            uint32_t a[2][4], b[4][2];
#pragma unroll
            for (int mt = 0; mt < 2; ++mt) {
                const int m0 = wm * 32 + mt * 16;
                a[mt][0] = xs[(m0 + gid    ) * SKX + k0 + tig    ];
                a[mt][1] = xs[(m0 + 8 + gid) * SKX + k0 + tig    ];
                a[mt][2] = xs[(m0 + gid    ) * SKX + k0 + 4 + tig];
                a[mt][3] = xs[(m0 + 8 + gid) * SKX + k0 + 4 + tig];
            }
#pragma unroll
            for (int nt = 0; nt < 4; ++nt) {
                const int n0 = wn * 32 + nt * 8;
                b[nt][0] = ws[(k0 + tig    ) * SNW + n0 + gid];
                b[nt][1] = ws[(k0 + 4 + tig) * SNW + n0 + gid];
            }
#pragma unroll
            for (int mt = 0; mt < 2; ++mt)
#pragma unroll
                for (int nt = 0; nt < 4; ++nt) {
                    asm volatile(
                        "mma.sync.aligned.m16n8k8.row.col.f32.tf32.tf32.f32 "
                        "{%0,%1,%2,%3}, {%4,%5,%6,%7}, {%8,%9}, {%0,%1,%2,%3};"
                        : "+f"(c[mt][nt][0]), "+f"(c[mt][nt][1]),
                          "+f"(c[mt][nt][2]), "+f"(c[mt][nt][3])
                        : "r"(a[mt][0]), "r"(a[mt][1]),
                          "r"(a[mt][2]), "r"(a[mt][3]),
                          "r"(b[nt][0]), "r"(b[nt][1]));
                }
        }
    }

    float2* hs2 = reinterpret_cast<float2*>(g_hs);
#pragma unroll
    for (int mt = 0; mt < 2; ++mt) {
        const int r0 = rowBase + wm * 32 + mt * 16 + gid;
        const int r1 = r0 + 8;
        const float dv0 = (r0 < N) ? g_dinv[r0] : 0.f;
        const float dv1 = (r1 < N) ? g_dinv[r1] : 0.f;
#pragma unroll
        for (int nt = 0; nt < 4; ++nt) {
            const int cpair = wn * 16 + nt * 4 + tig;
            if (r0 < N)
                hs2[(size_t)r0 * (COUT / 2) + cpair] =
                    make_float2(c[mt][nt][0] * dv0, c[mt][nt][1] * dv0);
            if (r1 < N)
                hs2[(size_t)r1 * (COUT / 2) + cpair] =
                    make_float2(c[mt][nt][2] * dv1, c[mt][nt][3] * dv1);
        }
    }
}

// ---------------------------------------------------------------------------
// K4: gather + finalize (atomic-free).
// 16 lanes per node, one float4 column chunk each. Register accumulation over
// the node's bucket; src ids broadcast via width-16 shuffles. Single store:
//   out[r][c] = dinv[r] * (sum_src hs[src][c] + hs[r][c]) + b[c]
// ---------------------------------------------------------------------------
__global__ __launch_bounds__(256) void gather_finalize_kernel(
    const float* __restrict__ b, float* __restrict__ out, int N)
{
    const int t    = blockIdx.x * blockDim.x + threadIdx.x;
    const int node = t >> 4;
    if (node >= N) return;
    const int c = threadIdx.x & 15;
    const unsigned gmask = 0xFFFFu << (threadIdx.x & 16);   // this half-warp

    const int   deg = min(g_deg[node], CAP);
    const float dv  = g_dinv[node];

    // self-loop term: dinv[r]^2 * h[r] after the final dv multiply
    float4 acc = __ldg(&g_hs[(size_t)node * (COUT / 4) + c]);

    const int base = node * CAP;
    int j0 = 0;
    // full chunks of 16 edges
    for (; j0 + 16 <= deg; j0 += 16) {
        const int sv = __ldg(&g_csr[base + j0 + c]);
#pragma unroll
        for (int i = 0; i < 16; ++i) {
            const int s = __shfl_sync(gmask, sv, i, 16);
            const float4 v = __ldg(&g_hs[(size_t)s * (COUT / 4) + c]);
            acc.x += v.x; acc.y += v.y; acc.z += v.z; acc.w += v.w;
        }
    }
    // tail
    if (j0 < deg) {
        const int myj = j0 + c;
        const int sv  = (myj < deg) ? __ldg(&g_csr[base + myj]) : 0;
        const int cnt = deg - j0;
        for (int i = 0; i < cnt; ++i) {
            const int s = __shfl_sync(gmask, sv, i, 16);
            const float4 v = __ldg(&g_hs[(size_t)s * (COUT / 4) + c]);
            acc.x += v.x; acc.y += v.y; acc.z += v.z; acc.w += v.w;
        }
    }

    const float4 bb = __ldg(&reinterpret_cast<const float4*>(b)[c]);
    reinterpret_cast<float4*>(out)[(size_t)node * (COUT / 4) + c] =
        make_float4(dv * acc.x + bb.x, dv * acc.y + bb.y,
                    dv * acc.z + bb.z, dv * acc.w + bb.w);
}

// ---------------------------------------------------------------------------
// Launch
// ---------------------------------------------------------------------------
extern "C" void kernel_launch(void* const* d_in, const int* in_sizes, int n_in,
                              void* d_out, int out_size) {
    const float* x  = (const float*)d_in[0];
    const int*   ei = (const int*)d_in[1];     // edge_index is int32 (JAX x64 off)
    const float* W  = (const float*)d_in[2];
    const float* b  = (const float*)d_in[3];
    float*       out = (float*)d_out;

    const int N = in_sizes[0] / CIN;
    const int E = in_sizes[1] / 2;

    zero_deg_kernel<<<(N + 255) / 256, 256>>>(N);
    csr_fill_kernel<<<(E + 255) / 256, 256>>>(ei, E);
    dinv_kernel<<<(N + 255) / 256, 256>>>(N);
    gemm_tf32_kernel<<<(N + 127) / 128, 256>>>(x, W, N);
    gather_finalize_kernel<<<(N * 16 + 255) / 256, 256>>>(b, out, N);
}